// round 1
// baseline (speedup 1.0000x reference)
#include <cuda_runtime.h>
#include <math.h>
#include <float.h>

// ---------------- problem constants ----------------
#define CH   512
#define HW   4096
constexpr long long CHW = (long long)CH * HW;     // 2,097,152
constexpr long long CC  = (long long)CH * CH;     // 262,144
constexpr long long PQ  = (long long)HW * HW;     // 16,777,216

// ---------------- device scratch (static, no allocations) ----------------
__device__ float g_Fcent[4 * 2097152];   // centered features: 0,1=content b0,b1 ; 2,3=style
__device__ float g_means[4 * 512];
__device__ float g_Cov[4 * 262144];
__device__ float g_sigma[4];
__device__ float g_Ybuf[2 * 1048576];    // NS ping-pong, 4 matrices each
__device__ float g_Zbuf[2 * 1048576];
__device__ float g_Tm[1048576];
__device__ float g_W[1048576];           // scaled whitening mats (4)
__device__ float g_Cm[2 * 262144];       // coloring mats (2)
__device__ float g_NC[4 * 2097152];      // whitened: 0,1 = nc ; 2,3 = ns
__device__ float g_NSt[2 * 2097152];     // ns transposed [pix][c]
__device__ float g_snorm[2 * 4096];
__device__ float g_rk[2 * 4096];         // 1/knorm
__device__ float g_M0[33554432];         // [2][4096][4096] 134MB
__device__ float g_Tb[33554432];         // box-filtered   134MB
__device__ int   g_idx[2 * 4096];
__device__ float g_pbs[2 * 16 * 4096];
__device__ int   g_pbi[2 * 16 * 4096];
__device__ float g_reasT[2 * 2097152];   // reassembled [pix][c]

// ---------------- generic tiled SGEMM ----------------
// C[z] = alpha * op(A[z]) @ op(B[z]) (+ diagAdd on diagonal) (+ bias[z*biasStride + row])
// !TA: A is [M,K] row-major ; TA: A is [K,M] row-major.
// !TB: B is [K,N] row-major ; TB: B is [N,K] row-major.
template<int BM, int BN, int BK, int TM, int TN, bool TA, bool TB>
__global__ void sgemm_kernel(const float* __restrict__ A, const float* __restrict__ B,
                             float* __restrict__ Cd,
                             int M, int N, int K,
                             long long sA, long long sB, long long sC,
                             float alpha, float diagAdd,
                             const float* __restrict__ bias, int biasStride)
{
    constexpr int THREADS = (BM / TM) * (BN / TN);
    __shared__ float As[BK][BM];
    __shared__ float Bs[BK][BN];
    const int tid  = threadIdx.x;
    const int tcol = tid % (BN / TN);
    const int trow = tid / (BN / TN);
    const int m0 = blockIdx.y * BM;
    const int n0 = blockIdx.x * BN;
    const float* Ab = A + (long long)blockIdx.z * sA;
    const float* Bb = B + (long long)blockIdx.z * sB;

    float acc[TM][TN];
#pragma unroll
    for (int i = 0; i < TM; i++)
#pragma unroll
        for (int j = 0; j < TN; j++) acc[i][j] = 0.f;

    for (int k0 = 0; k0 < K; k0 += BK) {
        constexpr int LA = BM * BK / THREADS;
#pragma unroll
        for (int l = 0; l < LA; l++) {
            int i = tid + l * THREADS;
            int m, kk;
            if (TA) { m = i % BM; kk = i / BM; As[kk][m] = Ab[(long long)(k0 + kk) * M + m0 + m]; }
            else    { kk = i % BK; m = i / BK; As[kk][m] = Ab[(long long)(m0 + m) * K + k0 + kk]; }
        }
        constexpr int LB = BN * BK / THREADS;
#pragma unroll
        for (int l = 0; l < LB; l++) {
            int i = tid + l * THREADS;
            int n, kk;
            if (TB) { kk = i % BK; n = i / BK; Bs[kk][n] = Bb[(long long)(n0 + n) * K + k0 + kk]; }
            else    { n = i % BN; kk = i / BN; Bs[kk][n] = Bb[(long long)(k0 + kk) * N + n0 + n]; }
        }
        __syncthreads();
#pragma unroll
        for (int kk = 0; kk < BK; kk++) {
            float ra[TM], rb[TN];
#pragma unroll
            for (int i = 0; i < TM; i++) ra[i] = As[kk][trow * TM + i];
#pragma unroll
            for (int j = 0; j < TN; j++) rb[j] = Bs[kk][tcol * TN + j];
#pragma unroll
            for (int i = 0; i < TM; i++)
#pragma unroll
                for (int j = 0; j < TN; j++)
                    acc[i][j] = fmaf(ra[i], rb[j], acc[i][j]);
        }
        __syncthreads();
    }

    float* Cb = Cd + (long long)blockIdx.z * sC;
#pragma unroll
    for (int i = 0; i < TM; i++) {
        int gm = m0 + trow * TM + i;
        float bv = bias ? bias[blockIdx.z * biasStride + gm] : 0.f;
#pragma unroll
        for (int j = 0; j < TN; j++) {
            int gn = n0 + tcol * TN + j;
            float v = alpha * acc[i][j] + bv;
            if (gm == gn) v += diagAdd;
            Cb[(long long)gm * N + gn] = v;
        }
    }
}

// ---------------- per-channel mean + center ----------------
__global__ void center_kernel(const float* __restrict__ content, const float* __restrict__ style,
                              float* __restrict__ Fcent, float* __restrict__ means)
{
    int c = blockIdx.x, g = blockIdx.y;
    const float* src = (g < 2 ? content + (long long)g * CHW : style + (long long)(g - 2) * CHW)
                       + (long long)c * HW;
    __shared__ float red[256];
    float s = 0.f;
    for (int i = threadIdx.x; i < HW; i += 256) s += src[i];
    red[threadIdx.x] = s; __syncthreads();
    for (int st = 128; st > 0; st >>= 1) {
        if (threadIdx.x < st) red[threadIdx.x] += red[threadIdx.x + st];
        __syncthreads();
    }
    float mean = red[0] * (1.f / HW);
    if (threadIdx.x == 0) means[g * CH + c] = mean;
    float* dst = Fcent + (long long)g * CHW + (long long)c * HW;
    for (int i = threadIdx.x; i < HW; i += 256) dst[i] = src[i] - mean;
}

// ---------------- power iteration for lambda_max (per cov) ----------------
__global__ void power_kernel(const float* __restrict__ Cov, float* __restrict__ sigma)
{
    int g = blockIdx.x;
    const float* A = Cov + (long long)g * CC;
    __shared__ float v[CH];
    __shared__ float red[CH];
    int t = threadIdx.x;
    v[t] = 1.f + 1e-4f * t;
    __syncthreads();
    float lam = 0.f;
    for (int it = 0; it < 40; it++) {
        float acc = 0.f;
        for (int k = 0; k < CH; k++) acc = fmaf(A[(long long)k * CH + t], v[k], acc); // symmetric => coalesced
        __syncthreads();
        red[t] = acc * acc; __syncthreads();
        for (int st = 256; st > 0; st >>= 1) {
            if (t < st) red[t] += red[t + st];
            __syncthreads();
        }
        float n2 = red[0];
        lam = sqrtf(n2);
        float inv = (n2 > 0.f) ? rsqrtf(n2) : 0.f;
        __syncthreads();
        v[t] = acc * inv;
        __syncthreads();
    }
    if (t == 0) sigma[g] = lam * 1.02f + 1e-20f;
}

// ---------------- Newton-Schulz init / rescale ----------------
__global__ void ns_init_kernel(const float* __restrict__ Cov, const float* __restrict__ sigma,
                               float* __restrict__ Y, float* __restrict__ Z)
{
    long long i = (long long)blockIdx.x * blockDim.x + threadIdx.x;
    if (i >= 4 * CC) return;
    int g = (int)(i / CC);
    long long r = i % CC;
    int row = (int)(r / CH), col = (int)(r % CH);
    Y[i] = Cov[i] / sigma[g];
    Z[i] = (row == col) ? 1.f : 0.f;
}

__global__ void scale_kernel(const float* __restrict__ Y, const float* __restrict__ Z,
                             const float* __restrict__ sigma,
                             float* __restrict__ W, float* __restrict__ Cm)
{
    long long i = (long long)blockIdx.x * blockDim.x + threadIdx.x;
    if (i >= 4 * CC) return;
    int g = (int)(i / CC);
    float sq = sqrtf(sigma[g]);
    W[i] = Z[i] / sq;                    // cov^{-1/2}
    if (g >= 2) Cm[i - 2 * CC] = Y[i] * sq; // cov^{+1/2} for style
}

// ---------------- transpose whitened style to [pix][c] ----------------
__global__ void transpose_kernel(const float* __restrict__ NC, float* __restrict__ NSt)
{
    __shared__ float tile[32][33];
    int b = blockIdx.z;
    int p0 = blockIdx.x * 32, c0 = blockIdx.y * 32;
    const float* src = NC + (long long)(2 + b) * CHW;
    tile[threadIdx.y][threadIdx.x] = src[(long long)(c0 + threadIdx.y) * HW + p0 + threadIdx.x];
    __syncthreads();
    NSt[(long long)b * CHW + (long long)(p0 + threadIdx.y) * CH + c0 + threadIdx.x] =
        tile[threadIdx.x][threadIdx.y];
}

// ---------------- per-pixel squared norms of whitened style ----------------
__global__ void snorm_kernel(const float* __restrict__ NSt, float* __restrict__ snorm)
{
    int gw = (blockIdx.x * blockDim.x + threadIdx.x) >> 5;
    int lane = threadIdx.x & 31;
    if (gw >= 2 * HW) return;
    int b = gw / HW, p = gw % HW;
    const float* row = NSt + (long long)b * CHW + (long long)p * CH;
    float s = 0.f;
    for (int c = lane; c < CH; c += 32) { float v = row[c]; s = fmaf(v, v, s); }
    for (int o = 16; o > 0; o >>= 1) s += __shfl_down_sync(0xffffffff, s, o);
    if (lane == 0) snorm[b * HW + p] = s;
}

__global__ void rknorm_kernel(const float* __restrict__ snorm, float* __restrict__ rk)
{
    int i = blockIdx.x * blockDim.x + threadIdx.x;
    if (i >= 2 * HW) return;
    int b = i / HW, p = i % HW;
    int py = p >> 6, px = p & 63;
    float sum = 0.f;
    for (int u = -1; u <= 1; u++)
        for (int v = -1; v <= 1; v++) {
            int yy = py + u, xx = px + v;
            if ((unsigned)yy < 64u && (unsigned)xx < 64u) sum += snorm[b * HW + yy * 64 + xx];
        }
    rk[i] = 1.f / (sqrtf(sum) + 1e-5f);
}

// ---------------- horizontal diagonal 3-box over M0 ----------------
__global__ void boxh_kernel(const float* __restrict__ M0, float* __restrict__ Tb)
{
    long long i = (long long)blockIdx.x * 256 + threadIdx.x;
    int b = blockIdx.y;
    const float* M = M0 + (long long)b * PQ;
    int p = (int)(i >> 12);
    int q = (int)(i & 4095);
    int px = p & 63, qx = q & 63;
    float s = 0.f;
#pragma unroll
    for (int v = -1; v <= 1; v++) {
        if ((unsigned)(px + v) < 64u && (unsigned)(qx + v) < 64u) s += M[i + (long long)v * 4097];
    }
    Tb[(long long)b * PQ + i] = s;
}

// ---------------- vertical diagonal 3-box + partial argmax over p-chunks ----------------
__global__ void argmax_part_kernel(const float* __restrict__ Tb, const float* __restrict__ rk,
                                   float* __restrict__ pbs, int* __restrict__ pbi)
{
    int b = blockIdx.z;
    int q = blockIdx.x * 256 + threadIdx.x;
    int pc = blockIdx.y;   // 16 chunks of 256 p's
    __shared__ float srk[256];
    srk[threadIdx.x] = rk[b * HW + pc * 256 + threadIdx.x];
    __syncthreads();
    const float* T = Tb + (long long)b * PQ;
    float best = -FLT_MAX; int bi = 0;
    for (int pp = 0; pp < 256; pp++) {
        int p = pc * 256 + pp;
        float s = 0.f;
#pragma unroll
        for (int u = -1; u <= 1; u++) {
            int row = p + 64 * u, col = q + 64 * u;
            if ((unsigned)row < (unsigned)HW && (unsigned)col < (unsigned)HW)
                s += T[(long long)row * HW + col];
        }
        float sc = s * srk[pp];
        if (sc > best) { best = sc; bi = p; }   // ascending p => first max kept
    }
    pbs[(b * 16 + pc) * HW + q] = best;
    pbi[(b * 16 + pc) * HW + q] = bi;
}

__global__ void argmax_comb_kernel(const float* __restrict__ pbs, const int* __restrict__ pbi,
                                   int* __restrict__ idx)
{
    int i = blockIdx.x * 256 + threadIdx.x;
    if (i >= 2 * HW) return;
    int b = i / HW, q = i % HW;
    float best = -FLT_MAX; int bi = 0;
    for (int k = 0; k < 16; k++) {
        float s = pbs[(b * 16 + k) * HW + q];
        int p = pbi[(b * 16 + k) * HW + q];
        if (s > best || (s == best && p < bi)) { best = s; bi = p; }
    }
    idx[b * HW + q] = bi;
}

// ---------------- gather best patches + overlap-add ----------------
__global__ void gather_kernel(const float* __restrict__ NSt, const int* __restrict__ idx,
                              float* __restrict__ reasT)
{
    int b = blockIdx.y, pix = blockIdx.x;
    int Y = pix >> 6, X = pix & 63;
    __shared__ int sp[9];
    if (threadIdx.x < 9) {
        int dx = threadIdx.x / 3, dy = threadIdx.x % 3;
        int y = Y + 1 - dx, x = X + 1 - dy;
        int pos = -1;
        if ((unsigned)y < 64u && (unsigned)x < 64u) {
            int p = idx[b * HW + y * 64 + x];
            int sy = (p >> 6) + dx - 1, sx = (p & 63) + dy - 1;
            if ((unsigned)sy < 64u && (unsigned)sx < 64u) pos = sy * 64 + sx;
        }
        sp[threadIdx.x] = pos;
    }
    __syncthreads();
    int cy = (Y == 0 || Y == 63) ? 2 : 3;
    int cx = (X == 0 || X == 63) ? 2 : 3;
    float inv = 1.f / (float)(cy * cx);
    const float* base = NSt + (long long)b * CHW;
    float* out = reasT + (long long)b * CHW + (long long)pix * CH;
    for (int c = threadIdx.x; c < CH; c += 128) {
        float a = 0.f;
#pragma unroll
        for (int k = 0; k < 9; k++) {
            int pos = sp[k];
            if (pos >= 0) a += base[(long long)pos * CH + c];
        }
        out[c] = a * inv;
    }
}

// ---------------- host orchestration ----------------
extern "C" void kernel_launch(void* const* d_in, const int* in_sizes, int n_in,
                              void* d_out, int out_size)
{
    (void)in_sizes; (void)n_in; (void)out_size;
    const float* content = (const float*)d_in[0];
    const float* style   = (const float*)d_in[1];
    float* out = (float*)d_out;

    float *Fcent, *means, *Cov, *sigma, *Yb, *Zb, *Tm, *W, *Cm, *NC, *NSt, *snorm, *rk, *M0, *Tb, *pbs, *reasT;
    int *idx, *pbi;
    cudaGetSymbolAddress((void**)&Fcent, g_Fcent);
    cudaGetSymbolAddress((void**)&means, g_means);
    cudaGetSymbolAddress((void**)&Cov,   g_Cov);
    cudaGetSymbolAddress((void**)&sigma, g_sigma);
    cudaGetSymbolAddress((void**)&Yb,    g_Ybuf);
    cudaGetSymbolAddress((void**)&Zb,    g_Zbuf);
    cudaGetSymbolAddress((void**)&Tm,    g_Tm);
    cudaGetSymbolAddress((void**)&W,     g_W);
    cudaGetSymbolAddress((void**)&Cm,    g_Cm);
    cudaGetSymbolAddress((void**)&NC,    g_NC);
    cudaGetSymbolAddress((void**)&NSt,   g_NSt);
    cudaGetSymbolAddress((void**)&snorm, g_snorm);
    cudaGetSymbolAddress((void**)&rk,    g_rk);
    cudaGetSymbolAddress((void**)&M0,    g_M0);
    cudaGetSymbolAddress((void**)&Tb,    g_Tb);
    cudaGetSymbolAddress((void**)&idx,   g_idx);
    cudaGetSymbolAddress((void**)&pbs,   g_pbs);
    cudaGetSymbolAddress((void**)&pbi,   g_pbi);
    cudaGetSymbolAddress((void**)&reasT, g_reasT);

    // 1) per-channel mean + center (content b0,b1 ; style b0,b1)
    center_kernel<<<dim3(CH, 4), 256>>>(content, style, Fcent, means);

    // 2) covariances: Cov[g] = Fcent[g] @ Fcent[g]^T / 4095   (M=N=512, K=4096)
    sgemm_kernel<64, 64, 16, 4, 4, false, true><<<dim3(8, 8, 4), 256>>>(
        Fcent, Fcent, Cov, 512, 512, 4096, CHW, CHW, CC, 1.f / 4095.f, 0.f, nullptr, 0);

    // 3) lambda_max estimate per cov
    power_kernel<<<4, 512>>>(Cov, sigma);

    // 4) Newton-Schulz: Y->cov_n^{1/2}, Z->cov_n^{-1/2}
    ns_init_kernel<<<4096, 256>>>(Cov, sigma, Yb, Zb);
    float* Yc = Yb;            float* Yn = Yb + 4 * CC;
    float* Zc = Zb;            float* Zn = Zb + 4 * CC;
    for (int it = 0; it < 12; it++) {
        // T = 1.5 I - 0.5 Z Y
        sgemm_kernel<64, 64, 16, 4, 4, false, false><<<dim3(8, 8, 4), 256>>>(
            Zc, Yc, Tm, 512, 512, 512, CC, CC, CC, -0.5f, 1.5f, nullptr, 0);
        // Y' = Y T ; Z' = T Z
        sgemm_kernel<64, 64, 16, 4, 4, false, false><<<dim3(8, 8, 4), 256>>>(
            Yc, Tm, Yn, 512, 512, 512, CC, CC, CC, 1.f, 0.f, nullptr, 0);
        sgemm_kernel<64, 64, 16, 4, 4, false, false><<<dim3(8, 8, 4), 256>>>(
            Tm, Zc, Zn, 512, 512, 512, CC, CC, CC, 1.f, 0.f, nullptr, 0);
        float* t;
        t = Yc; Yc = Yn; Yn = t;
        t = Zc; Zc = Zn; Zn = t;
    }
    // 5) rescale: W[g] = Z/sqrt(sigma) ; Cm[b] = Y*sqrt(sigma) for style
    scale_kernel<<<4096, 256>>>(Yc, Zc, sigma, W, Cm);

    // 6) apply whitening: NC[g] = W[g] @ Fcent[g]   (M=512, N=4096, K=512)
    sgemm_kernel<128, 128, 16, 8, 8, false, false><<<dim3(32, 4, 4), 256>>>(
        W, Fcent, NC, 512, 4096, 512, CC, CHW, CHW, 1.f, 0.f, nullptr, 0);

    // 7) transpose whitened style to [pix][c] + patch norms
    transpose_kernel<<<dim3(128, 16, 2), dim3(32, 32)>>>(NC, NSt);
    snorm_kernel<<<1024, 256>>>(NSt, snorm);
    rknorm_kernel<<<32, 256>>>(snorm, rk);

    // 8) M0[b] = ns[b]^T @ nc[b]   (M=N=4096, K=512) ; A = NC[2+b] accessed as [K,M]
    sgemm_kernel<128, 128, 16, 8, 8, true, false><<<dim3(32, 32, 2), 256>>>(
        NC + 2 * CHW, NC, M0, 4096, 4096, 512, CHW, CHW, PQ, 1.f, 0.f, nullptr, 0);

    // 9) diagonal 3x3 box filter (separable) + normalized argmax over p
    boxh_kernel<<<dim3(65536, 2), 256>>>(M0, Tb);
    argmax_part_kernel<<<dim3(16, 16, 2), 256>>>(Tb, rk, pbs, pbi);
    argmax_comb_kernel<<<32, 256>>>(pbs, pbi, idx);

    // 10) gather patches + overlap-add (writes [pix][c])
    gather_kernel<<<dim3(4096, 2), 128>>>(NSt, idx, reasT);

    // 11) color: out[b] = Cm[b] @ reass[b] + style_mean[b]  (B given as [N,K] => TB)
    sgemm_kernel<128, 128, 16, 8, 8, false, true><<<dim3(32, 4, 2), 256>>>(
        Cm, reasT, out, 512, 4096, 512, CC, CHW, CHW, 1.f, 0.f, means + 2 * CH, CH);
}

// round 2
// speedup vs baseline: 1.7089x; 1.7089x over previous
#include <cuda_runtime.h>
#include <math.h>
#include <float.h>

// ---------------- problem constants ----------------
#define CH   512
#define HW   4096
constexpr long long CHW = (long long)CH * HW;     // 2,097,152
constexpr long long CC  = (long long)CH * CH;     // 262,144
constexpr long long PQ  = (long long)HW * HW;     // 16,777,216

// ---------------- device scratch (static, no allocations) ----------------
__device__ float g_Fcent[4 * 2097152];
__device__ float g_means[4 * 512];
__device__ float g_Cov[4 * 262144];
__device__ float g_sigma[4];
__device__ float g_Ybuf[2 * 1048576];
__device__ float g_Zbuf[2 * 1048576];
__device__ float g_Tm[1048576];
__device__ float g_W[1048576];
__device__ float g_Cm[2 * 262144];
__device__ float g_NC[4 * 2097152];
__device__ float g_NSt[2 * 2097152];
__device__ float g_snorm[2 * 4096];
__device__ float g_rk[2 * 4096];
__device__ float g_M0[33554432];
__device__ float g_Tb[33554432];
__device__ int   g_idx[2 * 4096];
__device__ float g_pbs[2 * 16 * 4096];
__device__ int   g_pbi[2 * 16 * 4096];
__device__ float g_reasT[2 * 2097152];

// ---------------- packed f32x2 helpers ----------------
typedef unsigned long long u64;
__device__ __forceinline__ u64 pack2(float x) {
    u64 r; asm("mov.b64 %0, {%1, %1};" : "=l"(r) : "f"(x)); return r;
}
__device__ __forceinline__ void ffma2(u64 &d, u64 a, u64 b) {
    asm("fma.rn.f32x2 %0, %1, %2, %3;" : "=l"(d) : "l"(a), "l"(b), "l"(d));
}
__device__ __forceinline__ float2 unpack2(u64 v) {
    float2 f; asm("mov.b64 {%0, %1}, %2;" : "=f"(f.x), "=f"(f.y) : "l"(v)); return f;
}

// ---------------- tiled SGEMM with packed f32x2 inner loop ----------------
// C = alpha * op(A) @ op(B) (+ diagAdd on diagonal) (+ bias[row])
// !TA: A is [M,K] row-major ; TA: A is [K,M] row-major.
// !TB: B is [K,N] row-major ; TB: B is [N,K] row-major.
template<int BM, int BN, int BK, int TM, int TN, bool TA, bool TB>
__device__ __forceinline__ void sgemm_tile(
    const float* __restrict__ Ab, const float* __restrict__ Bb, float* __restrict__ Cb,
    int M, int N, int K, float alpha, float diagAdd, const float* __restrict__ bias)
{
    constexpr int THREADS = (BM / TM) * (BN / TN);
    __shared__ float As[BK][BM + 4];
    __shared__ float Bs[BK][BN + 4];
    const int tid  = threadIdx.x;
    const int tcol = tid % (BN / TN);
    const int trow = tid / (BN / TN);
    const int m0 = blockIdx.y * BM;
    const int n0 = blockIdx.x * BN;

    u64 acc[TM][TN / 2];
#pragma unroll
    for (int i = 0; i < TM; i++)
#pragma unroll
        for (int j = 0; j < TN / 2; j++) acc[i][j] = 0ull;

    for (int k0 = 0; k0 < K; k0 += BK) {
        constexpr int LA4 = BM * BK / (4 * THREADS);
#pragma unroll
        for (int l = 0; l < LA4; l++) {
            int i = tid + l * THREADS;
            if (TA) {
                int kk = i / (BM / 4); int m = (i % (BM / 4)) * 4;
                *(float4*)&As[kk][m] = *(const float4*)&Ab[(long long)(k0 + kk) * M + m0 + m];
            } else {
                int m = i / (BK / 4); int kk = (i % (BK / 4)) * 4;
                float4 v = *(const float4*)&Ab[(long long)(m0 + m) * K + k0 + kk];
                As[kk + 0][m] = v.x; As[kk + 1][m] = v.y; As[kk + 2][m] = v.z; As[kk + 3][m] = v.w;
            }
        }
        constexpr int LB4 = BN * BK / (4 * THREADS);
#pragma unroll
        for (int l = 0; l < LB4; l++) {
            int i = tid + l * THREADS;
            if (TB) {
                int n = i / (BK / 4); int kk = (i % (BK / 4)) * 4;
                float4 v = *(const float4*)&Bb[(long long)(n0 + n) * K + k0 + kk];
                Bs[kk + 0][n] = v.x; Bs[kk + 1][n] = v.y; Bs[kk + 2][n] = v.z; Bs[kk + 3][n] = v.w;
            } else {
                int kk = i / (BN / 4); int n = (i % (BN / 4)) * 4;
                *(float4*)&Bs[kk][n] = *(const float4*)&Bb[(long long)(k0 + kk) * N + n0 + n];
            }
        }
        __syncthreads();
#pragma unroll
        for (int kk = 0; kk < BK; kk++) {
            float ra[TM];
#pragma unroll
            for (int i4 = 0; i4 < TM / 4; i4++) {
                float4 a4 = *(const float4*)&As[kk][trow * TM + i4 * 4];
                ra[i4 * 4 + 0] = a4.x; ra[i4 * 4 + 1] = a4.y;
                ra[i4 * 4 + 2] = a4.z; ra[i4 * 4 + 3] = a4.w;
            }
            u64 rb2[TN / 2];
#pragma unroll
            for (int j4 = 0; j4 < TN / 4; j4++) {
                ulonglong2 b2 = *(const ulonglong2*)&Bs[kk][tcol * TN + j4 * 4];
                rb2[j4 * 2 + 0] = b2.x; rb2[j4 * 2 + 1] = b2.y;
            }
#pragma unroll
            for (int i = 0; i < TM; i++) {
                u64 a2 = pack2(ra[i]);
#pragma unroll
                for (int j = 0; j < TN / 2; j++) ffma2(acc[i][j], a2, rb2[j]);
            }
        }
        __syncthreads();
    }

#pragma unroll
    for (int i = 0; i < TM; i++) {
        int gm = m0 + trow * TM + i;
        float bv = bias ? bias[gm] : 0.f;
#pragma unroll
        for (int j = 0; j < TN / 2; j++) {
            float2 v = unpack2(acc[i][j]);
            int gn = n0 + tcol * TN + 2 * j;
            float x = alpha * v.x + bv; if (gm == gn)     x += diagAdd;
            float y = alpha * v.y + bv; if (gm == gn + 1) y += diagAdd;
            float2 o; o.x = x; o.y = y;
            *(float2*)&Cb[(long long)gm * N + gn] = o;
        }
    }
}

template<int BM, int BN, int BK, int TM, int TN, bool TA, bool TB>
__global__ void sgemm_kernel(const float* __restrict__ A, const float* __restrict__ B,
                             float* __restrict__ C,
                             int M, int N, int K,
                             long long sA, long long sB, long long sC,
                             float alpha, float diagAdd,
                             const float* __restrict__ bias, int biasStride)
{
    const float* Ab = A + (long long)blockIdx.z * sA;
    const float* Bb = B + (long long)blockIdx.z * sB;
    float* Cb = C + (long long)blockIdx.z * sC;
    const float* bb = bias ? bias + (long long)blockIdx.z * biasStride : nullptr;
    sgemm_tile<BM, BN, BK, TM, TN, TA, TB>(Ab, Bb, Cb, M, N, K, alpha, diagAdd, bb);
}

// Merged NS update: z<4 -> Yn[z] = Y[z]@T[z] ; z>=4 -> Zn[z-4] = T[z-4]@Z[z-4]
__global__ void ns_yz_kernel(const float* __restrict__ Y, const float* __restrict__ T,
                             const float* __restrict__ Z,
                             float* __restrict__ Yn, float* __restrict__ Zn)
{
    int z = blockIdx.z;
    const float *Ab, *Bb; float* Cb;
    if (z < 4) { Ab = Y + (long long)z * CC;       Bb = T + (long long)z * CC;       Cb = Yn + (long long)z * CC; }
    else       { Ab = T + (long long)(z - 4) * CC; Bb = Z + (long long)(z - 4) * CC; Cb = Zn + (long long)(z - 4) * CC; }
    sgemm_tile<64, 64, 16, 4, 4, false, false>(Ab, Bb, Cb, 512, 512, 512, 1.f, 0.f, nullptr);
}

// ---------------- per-channel mean + center ----------------
__global__ void center_kernel(const float* __restrict__ content, const float* __restrict__ style,
                              float* __restrict__ Fcent, float* __restrict__ means)
{
    int c = blockIdx.x, g = blockIdx.y;
    const float* src = (g < 2 ? content + (long long)g * CHW : style + (long long)(g - 2) * CHW)
                       + (long long)c * HW;
    __shared__ float red[256];
    float s = 0.f;
    for (int i = threadIdx.x; i < HW; i += 256) s += src[i];
    red[threadIdx.x] = s; __syncthreads();
    for (int st = 128; st > 0; st >>= 1) {
        if (threadIdx.x < st) red[threadIdx.x] += red[threadIdx.x + st];
        __syncthreads();
    }
    float mean = red[0] * (1.f / HW);
    if (threadIdx.x == 0) means[g * CH + c] = mean;
    float* dst = Fcent + (long long)g * CHW + (long long)c * HW;
    for (int i = threadIdx.x; i < HW; i += 256) dst[i] = src[i] - mean;
}

// ---------------- power iteration for lambda_max ----------------
__global__ void power_kernel(const float* __restrict__ Cov, float* __restrict__ sigma)
{
    int g = blockIdx.x;
    const float* A = Cov + (long long)g * CC;
    __shared__ float v[CH];
    __shared__ float red[CH];
    int t = threadIdx.x;
    v[t] = 1.f + 1e-4f * t;
    __syncthreads();
    float lam = 0.f;
    for (int it = 0; it < 40; it++) {
        float acc = 0.f;
        for (int k = 0; k < CH; k++) acc = fmaf(A[(long long)k * CH + t], v[k], acc);
        __syncthreads();
        red[t] = acc * acc; __syncthreads();
        for (int st = 256; st > 0; st >>= 1) {
            if (t < st) red[t] += red[t + st];
            __syncthreads();
        }
        float n2 = red[0];
        lam = sqrtf(n2);
        float inv = (n2 > 0.f) ? rsqrtf(n2) : 0.f;
        __syncthreads();
        v[t] = acc * inv;
        __syncthreads();
    }
    if (t == 0) sigma[g] = lam * 1.02f + 1e-20f;
}

// ---------------- Newton-Schulz init / rescale ----------------
__global__ void ns_init_kernel(const float* __restrict__ Cov, const float* __restrict__ sigma,
                               float* __restrict__ Y, float* __restrict__ Z)
{
    long long i = (long long)blockIdx.x * blockDim.x + threadIdx.x;
    if (i >= 4 * CC) return;
    int g = (int)(i / CC);
    long long r = i % CC;
    int row = (int)(r / CH), col = (int)(r % CH);
    Y[i] = Cov[i] / sigma[g];
    Z[i] = (row == col) ? 1.f : 0.f;
}

__global__ void scale_kernel(const float* __restrict__ Y, const float* __restrict__ Z,
                             const float* __restrict__ sigma,
                             float* __restrict__ W, float* __restrict__ Cm)
{
    long long i = (long long)blockIdx.x * blockDim.x + threadIdx.x;
    if (i >= 4 * CC) return;
    int g = (int)(i / CC);
    float sq = sqrtf(sigma[g]);
    W[i] = Z[i] / sq;
    if (g >= 2) Cm[i - 2 * CC] = Y[i] * sq;
}

// ---------------- transpose whitened style to [pix][c] ----------------
__global__ void transpose_kernel(const float* __restrict__ NC, float* __restrict__ NSt)
{
    __shared__ float tile[32][33];
    int b = blockIdx.z;
    int p0 = blockIdx.x * 32, c0 = blockIdx.y * 32;
    const float* src = NC + (long long)(2 + b) * CHW;
    tile[threadIdx.y][threadIdx.x] = src[(long long)(c0 + threadIdx.y) * HW + p0 + threadIdx.x];
    __syncthreads();
    NSt[(long long)b * CHW + (long long)(p0 + threadIdx.y) * CH + c0 + threadIdx.x] =
        tile[threadIdx.x][threadIdx.y];
}

// ---------------- per-pixel squared norms ----------------
__global__ void snorm_kernel(const float* __restrict__ NSt, float* __restrict__ snorm)
{
    int gw = (blockIdx.x * blockDim.x + threadIdx.x) >> 5;
    int lane = threadIdx.x & 31;
    if (gw >= 2 * HW) return;
    int b = gw / HW, p = gw % HW;
    const float* row = NSt + (long long)b * CHW + (long long)p * CH;
    float s = 0.f;
    for (int c = lane; c < CH; c += 32) { float v = row[c]; s = fmaf(v, v, s); }
    for (int o = 16; o > 0; o >>= 1) s += __shfl_down_sync(0xffffffff, s, o);
    if (lane == 0) snorm[b * HW + p] = s;
}

__global__ void rknorm_kernel(const float* __restrict__ snorm, float* __restrict__ rk)
{
    int i = blockIdx.x * blockDim.x + threadIdx.x;
    if (i >= 2 * HW) return;
    int b = i / HW, p = i % HW;
    int py = p >> 6, px = p & 63;
    float sum = 0.f;
    for (int u = -1; u <= 1; u++)
        for (int v = -1; v <= 1; v++) {
            int yy = py + u, xx = px + v;
            if ((unsigned)yy < 64u && (unsigned)xx < 64u) sum += snorm[b * HW + yy * 64 + xx];
        }
    rk[i] = 1.f / (sqrtf(sum) + 1e-5f);
}

// ---------------- horizontal diagonal 3-box ----------------
__global__ void boxh_kernel(const float* __restrict__ M0, float* __restrict__ Tb)
{
    long long i = (long long)blockIdx.x * 256 + threadIdx.x;
    int b = blockIdx.y;
    const float* M = M0 + (long long)b * PQ;
    int p = (int)(i >> 12);
    int q = (int)(i & 4095);
    int px = p & 63, qx = q & 63;
    float s = 0.f;
#pragma unroll
    for (int v = -1; v <= 1; v++) {
        if ((unsigned)(px + v) < 64u && (unsigned)(qx + v) < 64u) s += M[i + (long long)v * 4097];
    }
    Tb[(long long)b * PQ + i] = s;
}

// ---------------- vertical diagonal 3-box + partial argmax ----------------
__global__ void argmax_part_kernel(const float* __restrict__ Tb, const float* __restrict__ rk,
                                   float* __restrict__ pbs, int* __restrict__ pbi)
{
    int b = blockIdx.z;
    int q = blockIdx.x * 256 + threadIdx.x;
    int pc = blockIdx.y;
    __shared__ float srk[256];
    srk[threadIdx.x] = rk[b * HW + pc * 256 + threadIdx.x];
    __syncthreads();
    const float* T = Tb + (long long)b * PQ;
    float best = -FLT_MAX; int bi = 0;
    for (int pp = 0; pp < 256; pp++) {
        int p = pc * 256 + pp;
        float s = 0.f;
#pragma unroll
        for (int u = -1; u <= 1; u++) {
            int row = p + 64 * u, col = q + 64 * u;
            if ((unsigned)row < (unsigned)HW && (unsigned)col < (unsigned)HW)
                s += T[(long long)row * HW + col];
        }
        float sc = s * srk[pp];
        if (sc > best) { best = sc; bi = p; }
    }
    pbs[(b * 16 + pc) * HW + q] = best;
    pbi[(b * 16 + pc) * HW + q] = bi;
}

__global__ void argmax_comb_kernel(const float* __restrict__ pbs, const int* __restrict__ pbi,
                                   int* __restrict__ idx)
{
    int i = blockIdx.x * 256 + threadIdx.x;
    if (i >= 2 * HW) return;
    int b = i / HW, q = i % HW;
    float best = -FLT_MAX; int bi = 0;
    for (int k = 0; k < 16; k++) {
        float s = pbs[(b * 16 + k) * HW + q];
        int p = pbi[(b * 16 + k) * HW + q];
        if (s > best || (s == best && p < bi)) { best = s; bi = p; }
    }
    idx[b * HW + q] = bi;
}

// ---------------- gather best patches + overlap-add ----------------
__global__ void gather_kernel(const float* __restrict__ NSt, const int* __restrict__ idx,
                              float* __restrict__ reasT)
{
    int b = blockIdx.y, pix = blockIdx.x;
    int Y = pix >> 6, X = pix & 63;
    __shared__ int sp[9];
    if (threadIdx.x < 9) {
        int dx = threadIdx.x / 3, dy = threadIdx.x % 3;
        int y = Y + 1 - dx, x = X + 1 - dy;
        int pos = -1;
        if ((unsigned)y < 64u && (unsigned)x < 64u) {
            int p = idx[b * HW + y * 64 + x];
            int sy = (p >> 6) + dx - 1, sx = (p & 63) + dy - 1;
            if ((unsigned)sy < 64u && (unsigned)sx < 64u) pos = sy * 64 + sx;
        }
        sp[threadIdx.x] = pos;
    }
    __syncthreads();
    int cy = (Y == 0 || Y == 63) ? 2 : 3;
    int cx = (X == 0 || X == 63) ? 2 : 3;
    float inv = 1.f / (float)(cy * cx);
    const float* base = NSt + (long long)b * CHW;
    float* out = reasT + (long long)b * CHW + (long long)pix * CH;
    for (int c = threadIdx.x; c < CH; c += 128) {
        float a = 0.f;
#pragma unroll
        for (int k = 0; k < 9; k++) {
            int pos = sp[k];
            if (pos >= 0) a += base[(long long)pos * CH + c];
        }
        out[c] = a * inv;
    }
}

// ---------------- host orchestration ----------------
extern "C" void kernel_launch(void* const* d_in, const int* in_sizes, int n_in,
                              void* d_out, int out_size)
{
    (void)in_sizes; (void)n_in; (void)out_size;
    const float* content = (const float*)d_in[0];
    const float* style   = (const float*)d_in[1];
    float* out = (float*)d_out;

    float *Fcent, *means, *Cov, *sigma, *Yb, *Zb, *Tm, *W, *Cm, *NC, *NSt, *snorm, *rk, *M0, *Tb, *pbs, *reasT;
    int *idx, *pbi;
    cudaGetSymbolAddress((void**)&Fcent, g_Fcent);
    cudaGetSymbolAddress((void**)&means, g_means);
    cudaGetSymbolAddress((void**)&Cov,   g_Cov);
    cudaGetSymbolAddress((void**)&sigma, g_sigma);
    cudaGetSymbolAddress((void**)&Yb,    g_Ybuf);
    cudaGetSymbolAddress((void**)&Zb,    g_Zbuf);
    cudaGetSymbolAddress((void**)&Tm,    g_Tm);
    cudaGetSymbolAddress((void**)&W,     g_W);
    cudaGetSymbolAddress((void**)&Cm,    g_Cm);
    cudaGetSymbolAddress((void**)&NC,    g_NC);
    cudaGetSymbolAddress((void**)&NSt,   g_NSt);
    cudaGetSymbolAddress((void**)&snorm, g_snorm);
    cudaGetSymbolAddress((void**)&rk,    g_rk);
    cudaGetSymbolAddress((void**)&M0,    g_M0);
    cudaGetSymbolAddress((void**)&Tb,    g_Tb);
    cudaGetSymbolAddress((void**)&idx,   g_idx);
    cudaGetSymbolAddress((void**)&pbs,   g_pbs);
    cudaGetSymbolAddress((void**)&pbi,   g_pbi);
    cudaGetSymbolAddress((void**)&reasT, g_reasT);

    // 1) center
    center_kernel<<<dim3(CH, 4), 256>>>(content, style, Fcent, means);

    // 2) covariances
    sgemm_kernel<64, 64, 16, 4, 4, false, true><<<dim3(8, 8, 4), 256>>>(
        Fcent, Fcent, Cov, 512, 512, 4096, CHW, CHW, CC, 1.f / 4095.f, 0.f, nullptr, 0);

    // 3) lambda_max
    power_kernel<<<4, 512>>>(Cov, sigma);

    // 4) Newton-Schulz (6 iterations: residual ~1e-14)
    ns_init_kernel<<<4096, 256>>>(Cov, sigma, Yb, Zb);
    float* Yc = Yb;            float* Yn = Yb + 4 * CC;
    float* Zc = Zb;            float* Zn = Zb + 4 * CC;
    for (int it = 0; it < 6; it++) {
        sgemm_kernel<64, 64, 16, 4, 4, false, false><<<dim3(8, 8, 4), 256>>>(
            Zc, Yc, Tm, 512, 512, 512, CC, CC, CC, -0.5f, 1.5f, nullptr, 0);
        ns_yz_kernel<<<dim3(8, 8, 8), 256>>>(Yc, Tm, Zc, Yn, Zn);
        float* t;
        t = Yc; Yc = Yn; Yn = t;
        t = Zc; Zc = Zn; Zn = t;
    }
    // 5) rescale
    scale_kernel<<<4096, 256>>>(Yc, Zc, sigma, W, Cm);

    // 6) whitening: NC[g] = W[g] @ Fcent[g]
    sgemm_kernel<128, 128, 16, 8, 8, false, false><<<dim3(32, 4, 4), 256>>>(
        W, Fcent, NC, 512, 4096, 512, CC, CHW, CHW, 1.f, 0.f, nullptr, 0);

    // 7) transpose + patch norms
    transpose_kernel<<<dim3(128, 16, 2), dim3(32, 32)>>>(NC, NSt);
    snorm_kernel<<<1024, 256>>>(NSt, snorm);
    rknorm_kernel<<<32, 256>>>(snorm, rk);

    // 8) M0[b] = ns[b]^T @ nc[b]
    sgemm_kernel<128, 128, 16, 8, 8, true, false><<<dim3(32, 32, 2), 256>>>(
        NC + 2 * CHW, NC, M0, 4096, 4096, 512, CHW, CHW, PQ, 1.f, 0.f, nullptr, 0);

    // 9) box filter + argmax
    boxh_kernel<<<dim3(65536, 2), 256>>>(M0, Tb);
    argmax_part_kernel<<<dim3(16, 16, 2), 256>>>(Tb, rk, pbs, pbi);
    argmax_comb_kernel<<<32, 256>>>(pbs, pbi, idx);

    // 10) gather + overlap-add
    gather_kernel<<<dim3(4096, 2), 128>>>(NSt, idx, reasT);

    // 11) color
    sgemm_kernel<128, 128, 16, 8, 8, false, true><<<dim3(32, 4, 2), 256>>>(
        Cm, reasT, out, 512, 4096, 512, CC, CHW, CHW, 1.f, 0.f, means + 2 * CH, CH);
}

// round 3
// speedup vs baseline: 1.7249x; 1.0094x over previous
#include <cuda_runtime.h>
#include <math.h>
#include <float.h>

// ---------------- problem constants ----------------
#define CH   512
#define HW   4096
constexpr long long CHW = (long long)CH * HW;
constexpr long long CC  = (long long)CH * CH;
constexpr long long PQ  = (long long)HW * HW;

// ---------------- device scratch ----------------
__device__ float g_Fcent[4 * 2097152];
__device__ float g_means[4 * 512];
__device__ float g_Cov[4 * 262144];
__device__ float g_sigma[4];
__device__ float g_Ybuf[2 * 1048576];
__device__ float g_Zbuf[2 * 1048576];
__device__ float g_Tm[1048576];
__device__ float g_W[1048576];
__device__ float g_Cm[2 * 262144];
__device__ float g_NC[4 * 2097152];
__device__ float g_NSt[2 * 2097152];
__device__ float g_snorm[2 * 4096];
__device__ float g_rk[2 * 4096];
__device__ float g_M0[33554432];
__device__ float g_Tb[33554432];
__device__ int   g_idx[2 * 4096];
__device__ float g_pbs[2 * 16 * 4096];
__device__ int   g_pbi[2 * 16 * 4096];
__device__ float g_reasT[2 * 2097152];

// ---------------- packed f32x2 helpers ----------------
typedef unsigned long long u64;
__device__ __forceinline__ u64 pack2(float x) {
    u64 r; asm("mov.b64 %0, {%1, %1};" : "=l"(r) : "f"(x)); return r;
}
__device__ __forceinline__ void ffma2(u64 &d, u64 a, u64 b) {
    asm("fma.rn.f32x2 %0, %1, %2, %3;" : "=l"(d) : "l"(a), "l"(b), "l"(d));
}
__device__ __forceinline__ float2 unpack2(u64 v) {
    float2 f; asm("mov.b64 {%0, %1}, %2;" : "=f"(f.x), "=f"(f.y) : "l"(v)); return f;
}

// ---------------- double-buffered pipelined SGEMM (f32x2 inner loop) ----------------
// C = alpha * op(A) @ op(B) (+ diagAdd on diagonal) (+ bias[row])
// !TA: A is [M,K] row-major ; TA: A is [K,M] row-major.
// !TB: B is [K,N] row-major ; TB: B is [N,K] row-major.
template<int BM, int BN, int BK, int TM, int TN, bool TA, bool TB>
__device__ __forceinline__ void sgemm_tile(
    const float* __restrict__ Ab, const float* __restrict__ Bb, float* __restrict__ Cb,
    int M, int N, int K, float alpha, float diagAdd, const float* __restrict__ bias)
{
    constexpr int THREADS = (BM / TM) * (BN / TN);
    constexpr int LA4 = BM * BK / (4 * THREADS);
    constexpr int LB4 = BN * BK / (4 * THREADS);
    __shared__ float As[2][BK][BM + 4];
    __shared__ float Bs[2][BK][BN + 4];
    const int tid  = threadIdx.x;
    const int tcol = tid % (BN / TN);
    const int trow = tid / (BN / TN);
    const int m0 = blockIdx.y * BM;
    const int n0 = blockIdx.x * BN;

    float4 stA[LA4], stB[LB4];

    auto loadA = [&](int k0) {
#pragma unroll
        for (int l = 0; l < LA4; l++) {
            int i = tid + l * THREADS;
            if (TA) { int kk = i / (BM / 4); int m = (i % (BM / 4)) * 4;
                      stA[l] = *(const float4*)&Ab[(long long)(k0 + kk) * M + m0 + m]; }
            else    { int m = i / (BK / 4); int kk = (i % (BK / 4)) * 4;
                      stA[l] = *(const float4*)&Ab[(long long)(m0 + m) * K + k0 + kk]; }
        }
    };
    auto loadB = [&](int k0) {
#pragma unroll
        for (int l = 0; l < LB4; l++) {
            int i = tid + l * THREADS;
            if (TB) { int n = i / (BK / 4); int kk = (i % (BK / 4)) * 4;
                      stB[l] = *(const float4*)&Bb[(long long)(n0 + n) * K + k0 + kk]; }
            else    { int kk = i / (BN / 4); int n = (i % (BN / 4)) * 4;
                      stB[l] = *(const float4*)&Bb[(long long)(k0 + kk) * N + n0 + n]; }
        }
    };
    auto storeA = [&](int buf) {
#pragma unroll
        for (int l = 0; l < LA4; l++) {
            int i = tid + l * THREADS;
            if (TA) { int kk = i / (BM / 4); int m = (i % (BM / 4)) * 4;
                      *(float4*)&As[buf][kk][m] = stA[l]; }
            else    { int m = i / (BK / 4); int kk = (i % (BK / 4)) * 4;
                      As[buf][kk + 0][m] = stA[l].x; As[buf][kk + 1][m] = stA[l].y;
                      As[buf][kk + 2][m] = stA[l].z; As[buf][kk + 3][m] = stA[l].w; }
        }
    };
    auto storeB = [&](int buf) {
#pragma unroll
        for (int l = 0; l < LB4; l++) {
            int i = tid + l * THREADS;
            if (TB) { int n = i / (BK / 4); int kk = (i % (BK / 4)) * 4;
                      Bs[buf][kk + 0][n] = stB[l].x; Bs[buf][kk + 1][n] = stB[l].y;
                      Bs[buf][kk + 2][n] = stB[l].z; Bs[buf][kk + 3][n] = stB[l].w; }
            else    { int kk = i / (BN / 4); int n = (i % (BN / 4)) * 4;
                      *(float4*)&Bs[buf][kk][n] = stB[l]; }
        }
    };

    u64 acc[TM][TN / 2];
#pragma unroll
    for (int i = 0; i < TM; i++)
#pragma unroll
        for (int j = 0; j < TN / 2; j++) acc[i][j] = 0ull;

    loadA(0); loadB(0);
    storeA(0); storeB(0);
    __syncthreads();

    int buf = 0;
    for (int k0 = 0; k0 < K; k0 += BK) {
        const bool has_next = (k0 + BK < K);
        if (has_next) { loadA(k0 + BK); loadB(k0 + BK); }
#pragma unroll
        for (int kk = 0; kk < BK; kk++) {
            float ra[TM];
#pragma unroll
            for (int i4 = 0; i4 < TM / 4; i4++) {
                float4 a4 = *(const float4*)&As[buf][kk][trow * TM + i4 * 4];
                ra[i4 * 4 + 0] = a4.x; ra[i4 * 4 + 1] = a4.y;
                ra[i4 * 4 + 2] = a4.z; ra[i4 * 4 + 3] = a4.w;
            }
            u64 rb2[TN / 2];
#pragma unroll
            for (int j4 = 0; j4 < TN / 4; j4++) {
                ulonglong2 b2 = *(const ulonglong2*)&Bs[buf][kk][tcol * TN + j4 * 4];
                rb2[j4 * 2 + 0] = b2.x; rb2[j4 * 2 + 1] = b2.y;
            }
#pragma unroll
            for (int i = 0; i < TM; i++) {
                u64 a2 = pack2(ra[i]);
#pragma unroll
                for (int j = 0; j < TN / 2; j++) ffma2(acc[i][j], a2, rb2[j]);
            }
        }
        if (has_next) { storeA(buf ^ 1); storeB(buf ^ 1); }
        __syncthreads();
        buf ^= 1;
    }

#pragma unroll
    for (int i = 0; i < TM; i++) {
        int gm = m0 + trow * TM + i;
        float bv = bias ? bias[gm] : 0.f;
#pragma unroll
        for (int j = 0; j < TN / 2; j++) {
            float2 v = unpack2(acc[i][j]);
            int gn = n0 + tcol * TN + 2 * j;
            float x = alpha * v.x + bv; if (gm == gn)     x += diagAdd;
            float y = alpha * v.y + bv; if (gm == gn + 1) y += diagAdd;
            float2 o; o.x = x; o.y = y;
            *(float2*)&Cb[(long long)gm * N + gn] = o;
        }
    }
}

template<int BM, int BN, int BK, int TM, int TN, bool TA, bool TB>
__global__ void sgemm_kernel(const float* __restrict__ A, const float* __restrict__ B,
                             float* __restrict__ C,
                             int M, int N, int K,
                             long long sA, long long sB, long long sC,
                             float alpha, float diagAdd,
                             const float* __restrict__ bias, int biasStride)
{
    const float* Ab = A + (long long)blockIdx.z * sA;
    const float* Bb = B + (long long)blockIdx.z * sB;
    float* Cb = C + (long long)blockIdx.z * sC;
    const float* bb = bias ? bias + (long long)blockIdx.z * biasStride : nullptr;
    sgemm_tile<BM, BN, BK, TM, TN, TA, TB>(Ab, Bb, Cb, M, N, K, alpha, diagAdd, bb);
}

// Merged NS update: z<4 -> Yn[z] = Y[z]@T[z] ; z>=4 -> Zn[z-4] = T[z-4]@Z[z-4]
__global__ void ns_yz_kernel(const float* __restrict__ Y, const float* __restrict__ T,
                             const float* __restrict__ Z,
                             float* __restrict__ Yn, float* __restrict__ Zn)
{
    int z = blockIdx.z;
    const float *Ab, *Bb; float* Cb;
    if (z < 4) { Ab = Y + (long long)z * CC;       Bb = T + (long long)z * CC;       Cb = Yn + (long long)z * CC; }
    else       { Ab = T + (long long)(z - 4) * CC; Bb = Z + (long long)(z - 4) * CC; Cb = Zn + (long long)(z - 4) * CC; }
    sgemm_tile<64, 64, 16, 8, 8, false, false>(Ab, Bb, Cb, 512, 512, 512, 1.f, 0.f, nullptr);
}

// ---------------- per-channel mean + center ----------------
__global__ void center_kernel(const float* __restrict__ content, const float* __restrict__ style,
                              float* __restrict__ Fcent, float* __restrict__ means)
{
    int c = blockIdx.x, g = blockIdx.y;
    const float* src = (g < 2 ? content + (long long)g * CHW : style + (long long)(g - 2) * CHW)
                       + (long long)c * HW;
    __shared__ float red[256];
    float s = 0.f;
    for (int i = threadIdx.x; i < HW; i += 256) s += src[i];
    red[threadIdx.x] = s; __syncthreads();
    for (int st = 128; st > 0; st >>= 1) {
        if (threadIdx.x < st) red[threadIdx.x] += red[threadIdx.x + st];
        __syncthreads();
    }
    float mean = red[0] * (1.f / HW);
    if (threadIdx.x == 0) means[g * CH + c] = mean;
    float* dst = Fcent + (long long)g * CHW + (long long)c * HW;
    for (int i = threadIdx.x; i < HW; i += 256) dst[i] = src[i] - mean;
}

// ---------------- power iteration for lambda_max ----------------
__global__ void power_kernel(const float* __restrict__ Cov, float* __restrict__ sigma)
{
    int g = blockIdx.x;
    const float* A = Cov + (long long)g * CC;
    __shared__ float v[CH];
    __shared__ float red[CH];
    int t = threadIdx.x;
    v[t] = 1.f + 1e-4f * t;
    __syncthreads();
    float lam = 0.f;
    for (int it = 0; it < 40; it++) {
        float acc = 0.f;
        for (int k = 0; k < CH; k++) acc = fmaf(A[(long long)k * CH + t], v[k], acc);
        __syncthreads();
        red[t] = acc * acc; __syncthreads();
        for (int st = 256; st > 0; st >>= 1) {
            if (t < st) red[t] += red[t + st];
            __syncthreads();
        }
        float n2 = red[0];
        lam = sqrtf(n2);
        float inv = (n2 > 0.f) ? rsqrtf(n2) : 0.f;
        __syncthreads();
        v[t] = acc * inv;
        __syncthreads();
    }
    if (t == 0) sigma[g] = lam * 1.02f + 1e-20f;
}

// ---------------- Newton-Schulz init / rescale ----------------
__global__ void ns_init_kernel(const float* __restrict__ Cov, const float* __restrict__ sigma,
                               float* __restrict__ Y, float* __restrict__ Z)
{
    long long i = (long long)blockIdx.x * blockDim.x + threadIdx.x;
    if (i >= 4 * CC) return;
    int g = (int)(i / CC);
    long long r = i % CC;
    int row = (int)(r / CH), col = (int)(r % CH);
    Y[i] = Cov[i] / sigma[g];
    Z[i] = (row == col) ? 1.f : 0.f;
}

__global__ void scale_kernel(const float* __restrict__ Y, const float* __restrict__ Z,
                             const float* __restrict__ sigma,
                             float* __restrict__ W, float* __restrict__ Cm)
{
    long long i = (long long)blockIdx.x * blockDim.x + threadIdx.x;
    if (i >= 4 * CC) return;
    int g = (int)(i / CC);
    float sq = sqrtf(sigma[g]);
    W[i] = Z[i] / sq;
    if (g >= 2) Cm[i - 2 * CC] = Y[i] * sq;
}

// ---------------- transpose whitened style to [pix][c] ----------------
__global__ void transpose_kernel(const float* __restrict__ NC, float* __restrict__ NSt)
{
    __shared__ float tile[32][33];
    int b = blockIdx.z;
    int p0 = blockIdx.x * 32, c0 = blockIdx.y * 32;
    const float* src = NC + (long long)(2 + b) * CHW;
    tile[threadIdx.y][threadIdx.x] = src[(long long)(c0 + threadIdx.y) * HW + p0 + threadIdx.x];
    __syncthreads();
    NSt[(long long)b * CHW + (long long)(p0 + threadIdx.y) * CH + c0 + threadIdx.x] =
        tile[threadIdx.x][threadIdx.y];
}

// ---------------- per-pixel squared norms ----------------
__global__ void snorm_kernel(const float* __restrict__ NSt, float* __restrict__ snorm)
{
    int gw = (blockIdx.x * blockDim.x + threadIdx.x) >> 5;
    int lane = threadIdx.x & 31;
    if (gw >= 2 * HW) return;
    int b = gw / HW, p = gw % HW;
    const float* row = NSt + (long long)b * CHW + (long long)p * CH;
    float s = 0.f;
    for (int c = lane; c < CH; c += 32) { float v = row[c]; s = fmaf(v, v, s); }
    for (int o = 16; o > 0; o >>= 1) s += __shfl_down_sync(0xffffffff, s, o);
    if (lane == 0) snorm[b * HW + p] = s;
}

__global__ void rknorm_kernel(const float* __restrict__ snorm, float* __restrict__ rk)
{
    int i = blockIdx.x * blockDim.x + threadIdx.x;
    if (i >= 2 * HW) return;
    int b = i / HW, p = i % HW;
    int py = p >> 6, px = p & 63;
    float sum = 0.f;
    for (int u = -1; u <= 1; u++)
        for (int v = -1; v <= 1; v++) {
            int yy = py + u, xx = px + v;
            if ((unsigned)yy < 64u && (unsigned)xx < 64u) sum += snorm[b * HW + yy * 64 + xx];
        }
    rk[i] = 1.f / (sqrtf(sum) + 1e-5f);
}

// ---------------- horizontal diagonal 3-box ----------------
__global__ void boxh_kernel(const float* __restrict__ M0, float* __restrict__ Tb)
{
    long long i = (long long)blockIdx.x * 256 + threadIdx.x;
    int b = blockIdx.y;
    const float* M = M0 + (long long)b * PQ;
    int p = (int)(i >> 12);
    int q = (int)(i & 4095);
    int px = p & 63, qx = q & 63;
    float s = 0.f;
#pragma unroll
    for (int v = -1; v <= 1; v++) {
        if ((unsigned)(px + v) < 64u && (unsigned)(qx + v) < 64u) s += M[i + (long long)v * 4097];
    }
    Tb[(long long)b * PQ + i] = s;
}

// ---------------- vertical diagonal 3-box + partial argmax ----------------
__global__ void argmax_part_kernel(const float* __restrict__ Tb, const float* __restrict__ rk,
                                   float* __restrict__ pbs, int* __restrict__ pbi)
{
    int b = blockIdx.z;
    int q = blockIdx.x * 256 + threadIdx.x;
    int pc = blockIdx.y;
    __shared__ float srk[256];
    srk[threadIdx.x] = rk[b * HW + pc * 256 + threadIdx.x];
    __syncthreads();
    const float* T = Tb + (long long)b * PQ;
    float best = -FLT_MAX; int bi = 0;
    for (int pp = 0; pp < 256; pp++) {
        int p = pc * 256 + pp;
        float s = 0.f;
#pragma unroll
        for (int u = -1; u <= 1; u++) {
            int row = p + 64 * u, col = q + 64 * u;
            if ((unsigned)row < (unsigned)HW && (unsigned)col < (unsigned)HW)
                s += T[(long long)row * HW + col];
        }
        float sc = s * srk[pp];
        if (sc > best) { best = sc; bi = p; }
    }
    pbs[(b * 16 + pc) * HW + q] = best;
    pbi[(b * 16 + pc) * HW + q] = bi;
}

__global__ void argmax_comb_kernel(const float* __restrict__ pbs, const int* __restrict__ pbi,
                                   int* __restrict__ idx)
{
    int i = blockIdx.x * 256 + threadIdx.x;
    if (i >= 2 * HW) return;
    int b = i / HW, q = i % HW;
    float best = -FLT_MAX; int bi = 0;
    for (int k = 0; k < 16; k++) {
        float s = pbs[(b * 16 + k) * HW + q];
        int p = pbi[(b * 16 + k) * HW + q];
        if (s > best || (s == best && p < bi)) { best = s; bi = p; }
    }
    idx[b * HW + q] = bi;
}

// ---------------- gather best patches + overlap-add ----------------
__global__ void gather_kernel(const float* __restrict__ NSt, const int* __restrict__ idx,
                              float* __restrict__ reasT)
{
    int b = blockIdx.y, pix = blockIdx.x;
    int Y = pix >> 6, X = pix & 63;
    __shared__ int sp[9];
    if (threadIdx.x < 9) {
        int dx = threadIdx.x / 3, dy = threadIdx.x % 3;
        int y = Y + 1 - dx, x = X + 1 - dy;
        int pos = -1;
        if ((unsigned)y < 64u && (unsigned)x < 64u) {
            int p = idx[b * HW + y * 64 + x];
            int sy = (p >> 6) + dx - 1, sx = (p & 63) + dy - 1;
            if ((unsigned)sy < 64u && (unsigned)sx < 64u) pos = sy * 64 + sx;
        }
        sp[threadIdx.x] = pos;
    }
    __syncthreads();
    int cy = (Y == 0 || Y == 63) ? 2 : 3;
    int cx = (X == 0 || X == 63) ? 2 : 3;
    float inv = 1.f / (float)(cy * cx);
    const float* base = NSt + (long long)b * CHW;
    float* out = reasT + (long long)b * CHW + (long long)pix * CH;
    for (int c = threadIdx.x; c < CH; c += 128) {
        float a = 0.f;
#pragma unroll
        for (int k = 0; k < 9; k++) {
            int pos = sp[k];
            if (pos >= 0) a += base[(long long)pos * CH + c];
        }
        out[c] = a * inv;
    }
}

// ---------------- host orchestration ----------------
extern "C" void kernel_launch(void* const* d_in, const int* in_sizes, int n_in,
                              void* d_out, int out_size)
{
    (void)in_sizes; (void)n_in; (void)out_size;
    const float* content = (const float*)d_in[0];
    const float* style   = (const float*)d_in[1];
    float* out = (float*)d_out;

    float *Fcent, *means, *Cov, *sigma, *Yb, *Zb, *Tm, *W, *Cm, *NC, *NSt, *snorm, *rk, *M0, *Tb, *pbs, *reasT;
    int *idx, *pbi;
    cudaGetSymbolAddress((void**)&Fcent, g_Fcent);
    cudaGetSymbolAddress((void**)&means, g_means);
    cudaGetSymbolAddress((void**)&Cov,   g_Cov);
    cudaGetSymbolAddress((void**)&sigma, g_sigma);
    cudaGetSymbolAddress((void**)&Yb,    g_Ybuf);
    cudaGetSymbolAddress((void**)&Zb,    g_Zbuf);
    cudaGetSymbolAddress((void**)&Tm,    g_Tm);
    cudaGetSymbolAddress((void**)&W,     g_W);
    cudaGetSymbolAddress((void**)&Cm,    g_Cm);
    cudaGetSymbolAddress((void**)&NC,    g_NC);
    cudaGetSymbolAddress((void**)&NSt,   g_NSt);
    cudaGetSymbolAddress((void**)&snorm, g_snorm);
    cudaGetSymbolAddress((void**)&rk,    g_rk);
    cudaGetSymbolAddress((void**)&M0,    g_M0);
    cudaGetSymbolAddress((void**)&Tb,    g_Tb);
    cudaGetSymbolAddress((void**)&idx,   g_idx);
    cudaGetSymbolAddress((void**)&pbs,   g_pbs);
    cudaGetSymbolAddress((void**)&pbi,   g_pbi);
    cudaGetSymbolAddress((void**)&reasT, g_reasT);

    // 1) center
    center_kernel<<<dim3(CH, 4), 256>>>(content, style, Fcent, means);

    // 2) covariances (TM=TN=8, 64-thread blocks, 256 blocks)
    sgemm_kernel<64, 64, 16, 8, 8, false, true><<<dim3(8, 8, 4), 64>>>(
        Fcent, Fcent, Cov, 512, 512, 4096, CHW, CHW, CC, 1.f / 4095.f, 0.f, nullptr, 0);

    // 3) lambda_max
    power_kernel<<<4, 512>>>(Cov, sigma);

    // 4) Newton-Schulz (6 iterations)
    ns_init_kernel<<<4096, 256>>>(Cov, sigma, Yb, Zb);
    float* Yc = Yb;            float* Yn = Yb + 4 * CC;
    float* Zc = Zb;            float* Zn = Zb + 4 * CC;
    for (int it = 0; it < 6; it++) {
        sgemm_kernel<64, 64, 16, 8, 8, false, false><<<dim3(8, 8, 4), 64>>>(
            Zc, Yc, Tm, 512, 512, 512, CC, CC, CC, -0.5f, 1.5f, nullptr, 0);
        ns_yz_kernel<<<dim3(8, 8, 8), 64>>>(Yc, Tm, Zc, Yn, Zn);
        float* t;
        t = Yc; Yc = Yn; Yn = t;
        t = Zc; Zc = Zn; Zn = t;
    }
    // 5) rescale
    scale_kernel<<<4096, 256>>>(Yc, Zc, sigma, W, Cm);

    // 6) whitening: NC[g] = W[g] @ Fcent[g]
    sgemm_kernel<128, 128, 16, 8, 8, false, false><<<dim3(32, 4, 4), 256>>>(
        W, Fcent, NC, 512, 4096, 512, CC, CHW, CHW, 1.f, 0.f, nullptr, 0);

    // 7) transpose + patch norms
    transpose_kernel<<<dim3(128, 16, 2), dim3(32, 32)>>>(NC, NSt);
    snorm_kernel<<<1024, 256>>>(NSt, snorm);
    rknorm_kernel<<<32, 256>>>(snorm, rk);

    // 8) M0[b] = ns[b]^T @ nc[b]
    sgemm_kernel<128, 128, 16, 8, 8, true, false><<<dim3(32, 32, 2), 256>>>(
        NC + 2 * CHW, NC, M0, 4096, 4096, 512, CHW, CHW, PQ, 1.f, 0.f, nullptr, 0);

    // 9) box filter + argmax
    boxh_kernel<<<dim3(65536, 2), 256>>>(M0, Tb);
    argmax_part_kernel<<<dim3(16, 16, 2), 256>>>(Tb, rk, pbs, pbi);
    argmax_comb_kernel<<<32, 256>>>(pbs, pbi, idx);

    // 10) gather + overlap-add
    gather_kernel<<<dim3(4096, 2), 128>>>(NSt, idx, reasT);

    // 11) color
    sgemm_kernel<128, 128, 16, 8, 8, false, true><<<dim3(32, 4, 2), 256>>>(
        Cm, reasT, out, 512, 4096, 512, CC, CHW, CHW, 1.f, 0.f, means + 2 * CH, CH);
}